// round 2
// baseline (speedup 1.0000x reference)
#include <cuda_runtime.h>

// Problem constants
#define B_      64
#define S_      512
#define EMB_    300
#define T_      16
#define K4_     75          // EMB_/4
#define FULL_   0xffffffffu

// Scratch: per-batch integer lengths (no cudaMalloc allowed)
__device__ int g_lens[B_];

// ---------------------------------------------------------------------------
// Kernel 1: text lengths.  One block per batch row.
// ---------------------------------------------------------------------------
__global__ void __launch_bounds__(256) lens_kernel(const int* __restrict__ text,
                                                   float* __restrict__ out_lens) {
    int b   = blockIdx.x;
    int tid = threadIdx.x;
    int cnt = 0;
    for (int s = tid; s < S_; s += 256)
        cnt += (text[b * S_ + s] != 0);
    #pragma unroll
    for (int o = 16; o; o >>= 1)
        cnt += __shfl_xor_sync(FULL_, cnt, o);
    __shared__ int sh[8];
    if ((tid & 31) == 0) sh[tid >> 5] = cnt;
    __syncthreads();
    if (tid == 0) {
        int t = 0;
        #pragma unroll
        for (int w = 0; w < 8; w++) t += sh[w];
        g_lens[b]   = t;
        out_lens[b] = (float)t;
    }
}

// ---------------------------------------------------------------------------
// Kernel 2: probs = embed[text] @ W + b.
// Block = 256 threads = 8 warps = 16 tokens.  Each warp handles 2 tokens:
// lanes 0-15 -> token A (j = lane), lanes 16-31 -> token B (j = lane&15).
// W is packed in SMEM as float4 W4[k][j] = (W[4k][j],W[4k+1][j],W[4k+2][j],W[4k+3][j])
// so one LDS.128 per lane covers 4 K-elements and is shared across both tokens.
// ---------------------------------------------------------------------------
__global__ void __launch_bounds__(256) probs_kernel(const int*   __restrict__ text,
                                                    const float* __restrict__ embed,
                                                    const float* __restrict__ W,
                                                    const float* __restrict__ bias,
                                                    float*       __restrict__ probs) {
    __shared__ float4 W4[K4_][T_];
    __shared__ float  bsh[T_];

    int tid = threadIdx.x;
    float* w4f = (float*)W4;
    // W is row-major [EMB_][T_] : element (d,j) -> W4[d/4][j] component d%4
    for (int idx = tid; idx < EMB_ * T_; idx += 256) {
        int d = idx / T_, j = idx - d * T_;
        w4f[((d >> 2) * T_ + j) * 4 + (d & 3)] = W[idx];
    }
    if (tid < T_) bsh[tid] = bias[tid];
    __syncthreads();

    int warp = tid >> 5, lane = tid & 31;
    int half = lane >> 4, j = lane & 15;
    int token = blockIdx.x * 16 + warp * 2 + half;

    int row = text[token];
    const float4* erow = (const float4*)(embed + (size_t)row * EMB_);

    float acc = bsh[j];
    #pragma unroll 5
    for (int k = 0; k < K4_; k++) {
        float4 e = erow[k];
        float4 w = W4[k][j];
        acc = fmaf(e.x, w.x, acc);
        acc = fmaf(e.y, w.y, acc);
        acc = fmaf(e.z, w.z, acc);
        acc = fmaf(e.w, w.w, acc);
    }
    probs[token * T_ + j] = acc;
}

// ---------------------------------------------------------------------------
// Kernel 3: CRF log-likelihood.  One warp per batch row.
// Forward algorithm in the exp domain with periodic max-rescale:
//   a_j = exp(alpha_j - L);   alpha_new_j = logsumexp_i(alpha_i + trans_ij) + emit_j
//   => a'_j = (sum_i a_i * E_ij) * exp(emit_j),  E_ij = exp(trans_ij)
// Probs tile (32 KB) is staged in SMEM; emit reads are conflict-free LDS.
// ---------------------------------------------------------------------------
__global__ void __launch_bounds__(32) crf_kernel(const float* __restrict__ probs,
                                                 const int*   __restrict__ tags,
                                                 const float* __restrict__ trans,
                                                 float*       __restrict__ out_ll) {
    __shared__ float shp[S_ * T_];

    int b    = blockIdx.x;
    int lane = threadIdx.x;
    int j    = lane & 15;
    int len  = g_lens[b];

    // Stage probs[b] into shared (2048 float4 loads spread over 32 lanes)
    {
        const float4* src = (const float4*)(probs + (size_t)b * S_ * T_);
        float4* dst = (float4*)shp;
        #pragma unroll 8
        for (int idx = lane; idx < (S_ * T_) / 4; idx += 32)
            dst[idx] = src[idx];
    }
    __syncwarp();

    // Per-lane column of exp(trans): E[i] = exp(trans[i][j])
    float E[T_];
    #pragma unroll
    for (int i = 0; i < T_; i++) E[i] = __expf(trans[i * T_ + j]);

    // alpha0
    float a0 = shp[j];
    float m = a0;
    #pragma unroll
    for (int o = 8; o; o >>= 1)
        m = fmaxf(m, __shfl_xor_sync(FULL_, m, o));
    float L = m;
    float a = __expf(a0 - m);

    int end = (len < S_) ? len : S_;
    for (int s = 1; s < end; s++) {
        float emit = shp[s * T_ + j];
        float p = __expf(emit);
        float v[T_];
        #pragma unroll
        for (int i = 0; i < T_; i++)
            v[i] = __shfl_sync(FULL_, a, i) * E[i];
        // 4-level tree sum (constant indices -> registers)
        #pragma unroll
        for (int st = 1; st < T_; st <<= 1)
            #pragma unroll
            for (int i = 0; i < T_; i += 2 * st)
                v[i] += v[i + st];
        a = v[0] * p;
        if ((s & 7) == 0) {             // rescale to avoid overflow
            float mm = a;
            #pragma unroll
            for (int o = 8; o; o >>= 1)
                mm = fmaxf(mm, __shfl_xor_sync(FULL_, mm, o));
            a *= __frcp_rn(mm);
            L += __logf(mm);
        }
    }

    // log_norm = L + log(sum_j a_j)   (lanes mirrored: reduce within 16-group)
    float ssum = a;
    #pragma unroll
    for (int o = 8; o; o >>= 1)
        ssum += __shfl_xor_sync(FULL_, ssum, o);
    float log_norm = L + __logf(ssum);

    // unary + binary scores (lane-strided over s)
    const int* tg = tags + b * S_;
    float sc = 0.f;
    for (int s = lane; s < S_; s += 32) {
        if (s < len) {
            int t = tg[s];
            sc += shp[s * T_ + t];
            if (s >= 1) sc += trans[tg[s - 1] * T_ + t];
        }
    }
    #pragma unroll
    for (int o = 16; o; o >>= 1)
        sc += __shfl_xor_sync(FULL_, sc, o);

    if (lane == 0) out_ll[b] = sc - log_norm;
}

// ---------------------------------------------------------------------------
// Launch.  Output layout: probs [0,524288) | lens [524288,524352) | ll [...,524416)
// ---------------------------------------------------------------------------
extern "C" void kernel_launch(void* const* d_in, const int* in_sizes, int n_in,
                              void* d_out, int out_size) {
    const int*   text  = (const int*)  d_in[0];
    const int*   tags  = (const int*)  d_in[1];
    const float* embed = (const float*)d_in[2];
    const float* W     = (const float*)d_in[3];
    const float* bias  = (const float*)d_in[4];
    const float* trans = (const float*)d_in[5];

    float* out      = (float*)d_out;
    float* probs    = out;
    float* out_lens = out + B_ * S_ * T_;
    float* out_ll   = out_lens + B_;

    lens_kernel <<<B_, 256>>>(text, out_lens);
    probs_kernel<<<(B_ * S_) / 16, 256>>>(text, embed, W, bias, probs);
    crf_kernel  <<<B_, 32>>>(probs, tags, trans, out_ll);
}

// round 4
// speedup vs baseline: 1.0869x; 1.0869x over previous
#include <cuda_runtime.h>

// Problem constants
#define B_      64
#define S_      512
#define EMB_    300
#define T_      16
#define K4_     75          // EMB_/4
#define C_      32          // chunks per batch
#define CS_     16          // steps per chunk
#define FULL_   0xffffffffu
#define LN16_   2.7725887222397811f

// Scratch: per-(batch,chunk) 16x16 transfer-matrix products (2 MB)
__device__ float g_M[B_ * C_ * 256];

// ---------------------------------------------------------------------------
// Kernel 1: probs = embed[text] @ W + b.
// Block = 256 threads = 8 warps = 16 tokens.  Each warp: 2 tokens
// (lanes 0-15 / 16-31), j = lane&15.  W packed as float4 in SMEM.
// ---------------------------------------------------------------------------
__global__ void __launch_bounds__(256) probs_kernel(const int*   __restrict__ text,
                                                    const float* __restrict__ embed,
                                                    const float* __restrict__ W,
                                                    const float* __restrict__ bias,
                                                    float*       __restrict__ probs) {
    __shared__ float4 W4[K4_][T_];
    __shared__ float  bsh[T_];

    int tid = threadIdx.x;
    float* w4f = (float*)W4;
    for (int idx = tid; idx < EMB_ * T_; idx += 256) {
        int d = idx / T_, j = idx - d * T_;
        w4f[((d >> 2) * T_ + j) * 4 + (d & 3)] = W[idx];
    }
    if (tid < T_) bsh[tid] = bias[tid];
    __syncthreads();

    int warp = tid >> 5, lane = tid & 31;
    int half = lane >> 4, j = lane & 15;
    int token = blockIdx.x * 16 + warp * 2 + half;

    int row = text[token];
    const float4* erow = (const float4*)(embed + (size_t)row * EMB_);

    float acc = bsh[j];
    #pragma unroll 5
    for (int k = 0; k < K4_; k++) {
        float4 e = erow[k];
        float4 w = W4[k][j];
        acc = fmaf(e.x, w.x, acc);
        acc = fmaf(e.y, w.y, acc);
        acc = fmaf(e.z, w.z, acc);
        acc = fmaf(e.w, w.w, acc);
    }
    probs[token * T_ + j] = acc;
}

// ---------------------------------------------------------------------------
// Kernel 2: per-(batch,chunk) transfer-matrix products.
// Matrix id m = b*32 + c.  One 16-lane half-warp per matrix, lane = row i,
// M[i][0..15] in registers.  Per step (t = c*16+dt, applied iff 1<=t<len):
//   N[i][j] = (sum_k M[i][k] * E[k][j]) * (exp(emit_t[j]) / 16)
// E[k][j] = exp(trans[k][j]) staged column-contiguous in SMEM (broadcast LDS).
// The 1/16 per applied step is undone in the combine kernel (n*ln16).
// ---------------------------------------------------------------------------
__global__ void __launch_bounds__(128) chunk_kernel(const int*   __restrict__ text,
                                                    const float* __restrict__ probs,
                                                    const float* __restrict__ trans) {
    __shared__ float Esh[256];       // Esh[j*16+k] = exp(trans[k][j])
    __shared__ float psh[4][512];    // per warp: [half*256 + dt*16 + j]

    int tid = threadIdx.x;
    for (int idx = tid; idx < 256; idx += 128) {
        int k = idx >> 4, j = idx & 15;
        Esh[j * 16 + k] = __expf(trans[idx]);       // idx = k*16+j
    }

    int warp = tid >> 5, lane = tid & 31;
    int half = lane >> 4, li = lane & 15;
    int m = blockIdx.x * 8 + warp * 2 + half;
    int b = m >> 5, c = m & (C_ - 1);

    // len for batch b (redundant per matrix; 2 KB from L2, off critical path)
    const int4* tx4 = (const int4*)(text + b * S_);
    int cnt = 0;
    #pragma unroll
    for (int q = 0; q < 8; q++) {                    // 128 int4 / 16 lanes
        int4 v = tx4[li + q * 16];
        cnt += (v.x != 0) + (v.y != 0) + (v.z != 0) + (v.w != 0);
    }
    #pragma unroll
    for (int o = 8; o; o >>= 1) cnt += __shfl_xor_sync(FULL_, cnt, o);
    int len = cnt;

    // Stage exp(emit)/16 for this chunk's 16 steps (256 consecutive floats)
    {
        const float4* p4 = (const float4*)(probs + ((size_t)b * S_ + c * CS_) * T_);
        float* myp = &psh[warp][half * 256];
        #pragma unroll
        for (int q = 0; q < 4; q++) {
            float4 v = p4[li + q * 16];
            int o4 = (li + q * 16) * 4;
            myp[o4 + 0] = __expf(v.x) * 0.0625f;
            myp[o4 + 1] = __expf(v.y) * 0.0625f;
            myp[o4 + 2] = __expf(v.z) * 0.0625f;
            myp[o4 + 3] = __expf(v.w) * 0.0625f;
        }
    }
    __syncthreads();

    // M = identity row li
    float M[16];
    #pragma unroll
    for (int j = 0; j < 16; j++) M[j] = (j == li) ? 1.f : 0.f;

    const float* myp = &psh[warp][half * 256];
    #pragma unroll 1
    for (int dt = 0; dt < CS_; dt++) {
        int t = c * CS_ + dt;
        if (t >= 1 && t < len) {
            const float4* pv = (const float4*)(myp + dt * 16);
            float4 pa = pv[0], pb = pv[1], pc = pv[2], pd = pv[3];
            float p[16] = {pa.x, pa.y, pa.z, pa.w,  pb.x, pb.y, pb.z, pb.w,
                           pc.x, pc.y, pc.z, pc.w,  pd.x, pd.y, pd.z, pd.w};
            float N[16];
            #pragma unroll
            for (int j = 0; j < 16; j++) {
                const float4* e4 = (const float4*)(Esh + j * 16);
                float4 e0 = e4[0], e1 = e4[1], e2 = e4[2], e3 = e4[3];
                float acc;
                acc = M[0]  * e0.x;
                acc = fmaf(M[1],  e0.y, acc);
                acc = fmaf(M[2],  e0.z, acc);
                acc = fmaf(M[3],  e0.w, acc);
                acc = fmaf(M[4],  e1.x, acc);
                acc = fmaf(M[5],  e1.y, acc);
                acc = fmaf(M[6],  e1.z, acc);
                acc = fmaf(M[7],  e1.w, acc);
                acc = fmaf(M[8],  e2.x, acc);
                acc = fmaf(M[9],  e2.y, acc);
                acc = fmaf(M[10], e2.z, acc);
                acc = fmaf(M[11], e2.w, acc);
                acc = fmaf(M[12], e3.x, acc);
                acc = fmaf(M[13], e3.y, acc);
                acc = fmaf(M[14], e3.z, acc);
                acc = fmaf(M[15], e3.w, acc);
                N[j] = acc * p[j];
            }
            #pragma unroll
            for (int j = 0; j < 16; j++) M[j] = N[j];
        }
    }

    // Store row li of matrix m
    float4* out4 = (float4*)(g_M + (size_t)m * 256 + li * 16);
    out4[0] = make_float4(M[0],  M[1],  M[2],  M[3]);
    out4[1] = make_float4(M[4],  M[5],  M[6],  M[7]);
    out4[2] = make_float4(M[8],  M[9],  M[10], M[11]);
    out4[3] = make_float4(M[12], M[13], M[14], M[15]);
}

// ---------------------------------------------------------------------------
// Kernel 3: combine — 32 serial mat-vecs per batch + lens + scores.
// One warp per batch row.  lanes mirrored: j = lane & 15.
// ---------------------------------------------------------------------------
__global__ void __launch_bounds__(32) combine_kernel(const int*   __restrict__ text,
                                                     const int*   __restrict__ tags,
                                                     const float* __restrict__ probs,
                                                     const float* __restrict__ trans,
                                                     float*       __restrict__ out_lens,
                                                     float*       __restrict__ out_ll) {
    int b    = blockIdx.x;
    int lane = threadIdx.x;
    int j    = lane & 15;

    // lens
    const int4* tx4 = (const int4*)(text + b * S_);
    int cnt = 0;
    #pragma unroll
    for (int q = 0; q < 4; q++) {                    // 128 int4 / 32 lanes
        int4 v = tx4[lane + q * 32];
        cnt += (v.x != 0) + (v.y != 0) + (v.z != 0) + (v.w != 0);
    }
    #pragma unroll
    for (int o = 16; o; o >>= 1) cnt += __shfl_xor_sync(FULL_, cnt, o);
    int len = cnt;
    if (lane == 0) out_lens[b] = (float)len;

    const float* pb = probs + (size_t)b * S_ * T_;

    // alpha0 in scaled exp domain
    float a0 = pb[j];
    float mx = a0;
    #pragma unroll
    for (int o = 8; o; o >>= 1) mx = fmaxf(mx, __shfl_xor_sync(FULL_, mx, o));
    float L = mx;
    float a = __expf(a0 - mx);

    const float* Mb = g_M + (size_t)b * C_ * 256;
    #pragma unroll 1
    for (int c = 0; c < C_; c++) {
        int t0 = (c == 0) ? 1 : c * CS_;
        int hi = c * CS_ + CS_ - 1;
        int te = (len - 1 < hi) ? len - 1 : hi;
        int n  = te - t0 + 1;
        if (n > 0) {
            const float* Mc = Mb + c * 256;
            float v[16];
            #pragma unroll
            for (int i = 0; i < 16; i++)
                v[i] = __shfl_sync(FULL_, a, i) * Mc[i * 16 + j];
            #pragma unroll
            for (int st = 1; st < 16; st <<= 1)
                #pragma unroll
                for (int i = 0; i < 16; i += 2 * st)
                    v[i] += v[i + st];
            a = v[0];
            L += (float)n * LN16_;
            // rescale
            float mm = a;
            #pragma unroll
            for (int o = 8; o; o >>= 1) mm = fmaxf(mm, __shfl_xor_sync(FULL_, mm, o));
            a *= __frcp_rn(mm);
            L += __logf(mm);
        }
    }

    float ssum = a;
    #pragma unroll
    for (int o = 8; o; o >>= 1) ssum += __shfl_xor_sync(FULL_, ssum, o);
    float log_norm = L + __logf(ssum);

    // unary + binary scores
    const int* tg = tags + b * S_;
    float sc = 0.f;
    for (int s = lane; s < S_; s += 32) {
        if (s < len) {
            int t = tg[s];
            sc += pb[s * T_ + t];
            if (s >= 1) sc += trans[tg[s - 1] * T_ + t];
        }
    }
    #pragma unroll
    for (int o = 16; o; o >>= 1) sc += __shfl_xor_sync(FULL_, sc, o);

    if (lane == 0) out_ll[b] = sc - log_norm;
}

// ---------------------------------------------------------------------------
// Launch.  Output layout: probs [0,524288) | lens [524288,524352) | ll [...)
// ---------------------------------------------------------------------------
extern "C" void kernel_launch(void* const* d_in, const int* in_sizes, int n_in,
                              void* d_out, int out_size) {
    const int*   text  = (const int*)  d_in[0];
    const int*   tags  = (const int*)  d_in[1];
    const float* embed = (const float*)d_in[2];
    const float* W     = (const float*)d_in[3];
    const float* bias  = (const float*)d_in[4];
    const float* trans = (const float*)d_in[5];

    float* out      = (float*)d_out;
    float* probs    = out;
    float* out_lens = out + B_ * S_ * T_;
    float* out_ll   = out_lens + B_;

    probs_kernel  <<<(B_ * S_) / 16, 256>>>(text, embed, W, bias, probs);
    chunk_kernel  <<<(B_ * C_) / 8, 128>>>(text, probs, trans);
    combine_kernel<<<B_, 32>>>(text, tags, probs, trans, out_lens, out_ll);
}

// round 5
// speedup vs baseline: 1.3946x; 1.2832x over previous
#include <cuda_runtime.h>

// Problem constants
#define B_      64
#define S_      512
#define EMB_    300
#define T_      16
#define K4_     75          // EMB_/4
#define C_      32          // chunks per batch
#define CS_     16          // steps per chunk
#define FULL_   0xffffffffu
#define LN16_   2.7725887222397811f

// Packed f32x2 helpers (ptxas will not auto-fuse; must use PTX)
#define FMA2(d, a, b, c) asm("fma.rn.f32x2 %0, %1, %2, %3;" : "=l"(d) : "l"(a), "l"(b), "l"(c))
#define MUL2(d, a, b)    asm("mul.rn.f32x2 %0, %1, %2;"     : "=l"(d) : "l"(a), "l"(b))
#define ADD2(d, a, b)    asm("add.rn.f32x2 %0, %1, %2;"     : "=l"(d) : "l"(a), "l"(b))
#define PACK2(d, lo, hi) asm("mov.b64 %0, {%1, %2};"        : "=l"(d) : "f"(lo), "f"(hi))

__device__ __forceinline__ float2 unpack2(unsigned long long v) {
    float2 f;
    asm("mov.b64 {%0, %1}, %2;" : "=f"(f.x), "=f"(f.y) : "l"(v));
    return f;
}

// Scratch: per-(batch,chunk) 16x16 transfer-matrix products, stored TRANSPOSED:
// g_M[m*256 + j*16 + i] = M_m[i][j]   (column j contiguous over i)
__device__ float g_M[B_ * C_ * 256];

// ---------------------------------------------------------------------------
// Kernel 1: probs = embed[text] @ W + b.
// Warp = 16 tokens: two 16-lane halves, each half shares 8 tokens; j = lane&15.
// Per k-iter per warp: 8 LDG.128 (e, half-uniform addresses) + 1 LDS.128 (W)
// feeding 16 f32x2 FMAs -> mem-instr count ~1.8x lower than 2-token scheme.
// ---------------------------------------------------------------------------
__global__ void __launch_bounds__(256) probs_kernel(const int*   __restrict__ text,
                                                    const float* __restrict__ embed,
                                                    const float* __restrict__ W,
                                                    const float* __restrict__ bias,
                                                    float*       __restrict__ probs) {
    __shared__ ulonglong2 W4[K4_][T_];   // W4[k][j] = packed (W[4k..4k+3][j])
    __shared__ float      bsh[T_];

    int tid = threadIdx.x;
    float* wf = (float*)W4;
    for (int idx = tid; idx < EMB_ * T_; idx += 256) {
        int d = idx / T_, j = idx - d * T_;
        wf[((d >> 2) * T_ + j) * 4 + (d & 3)] = W[idx];
    }
    if (tid < T_) bsh[tid] = bias[tid];
    __syncthreads();

    int warp = tid >> 5, lane = tid & 31;
    int half = lane >> 4, j = lane & 15;
    int tb = blockIdx.x * 128 + warp * 16 + half * 8;

    const ulonglong2* ep[8];
    #pragma unroll
    for (int t = 0; t < 8; t++)
        ep[t] = (const ulonglong2*)(embed + (size_t)text[tb + t] * EMB_);

    unsigned long long acc[8];
    #pragma unroll
    for (int t = 0; t < 8; t++) acc[t] = 0ull;   // (0.f, 0.f)

    #pragma unroll 5
    for (int k = 0; k < K4_; k++) {
        ulonglong2 w = W4[k][j];
        #pragma unroll
        for (int t = 0; t < 8; t++) {
            ulonglong2 e = ep[t][k];
            FMA2(acc[t], e.x, w.x, acc[t]);
            FMA2(acc[t], e.y, w.y, acc[t]);
        }
    }

    #pragma unroll
    for (int t = 0; t < 8; t++) {
        float2 f = unpack2(acc[t]);
        probs[(size_t)(tb + t) * T_ + j] = f.x + f.y + bsh[j];
    }
}

// ---------------------------------------------------------------------------
// Kernel 2: per-(batch,chunk) transfer-matrix products (f32x2 mainloop).
// Matrix id m = b*32 + c.  One 16-lane half-warp per matrix, lane = row i.
//   N[i][j] = (sum_k M[i][k] * E[k][j]) * (exp(emit_t[j]) / 16)
// Result stored transposed into g_M for the combine kernel.
// ---------------------------------------------------------------------------
__global__ void __launch_bounds__(128) chunk_kernel(const int*   __restrict__ text,
                                                    const float* __restrict__ probs,
                                                    const float* __restrict__ trans) {
    __shared__ float Esh[256];       // Esh[j*16+k] = exp(trans[k][j])
    __shared__ float psh[4][512];    // per warp: [half*256 + dt*16 + j]

    int tid = threadIdx.x;
    for (int idx = tid; idx < 256; idx += 128) {
        int k = idx >> 4, jj = idx & 15;
        Esh[jj * 16 + k] = __expf(trans[idx]);
    }

    int warp = tid >> 5, lane = tid & 31;
    int half = lane >> 4, li = lane & 15;
    int m = blockIdx.x * 8 + warp * 2 + half;
    int b = m >> 5, c = m & (C_ - 1);

    // len for batch b
    const int4* tx4 = (const int4*)(text + b * S_);
    int cnt = 0;
    #pragma unroll
    for (int q = 0; q < 8; q++) {
        int4 v = tx4[li + q * 16];
        cnt += (v.x != 0) + (v.y != 0) + (v.z != 0) + (v.w != 0);
    }
    #pragma unroll
    for (int o = 8; o; o >>= 1) cnt += __shfl_xor_sync(FULL_, cnt, o);
    int len = cnt;

    // Stage exp(emit)/16 for this chunk's 16 steps
    {
        const float4* p4 = (const float4*)(probs + ((size_t)b * S_ + c * CS_) * T_);
        float* myp = &psh[warp][half * 256];
        #pragma unroll
        for (int q = 0; q < 4; q++) {
            float4 v = p4[li + q * 16];
            int o4 = (li + q * 16) * 4;
            myp[o4 + 0] = __expf(v.x) * 0.0625f;
            myp[o4 + 1] = __expf(v.y) * 0.0625f;
            myp[o4 + 2] = __expf(v.z) * 0.0625f;
            myp[o4 + 3] = __expf(v.w) * 0.0625f;
        }
    }
    __syncthreads();

    float M[16];
    #pragma unroll
    for (int jj = 0; jj < 16; jj++) M[jj] = (jj == li) ? 1.f : 0.f;

    const float* myp = &psh[warp][half * 256];
    #pragma unroll 1
    for (int dt = 0; dt < CS_; dt++) {
        int t = c * CS_ + dt;
        if (t >= 1 && t < len) {
            const float4* pv = (const float4*)(myp + dt * 16);
            float4 pa = pv[0], pb = pv[1], pc = pv[2], pd = pv[3];
            float p[16] = {pa.x, pa.y, pa.z, pa.w,  pb.x, pb.y, pb.z, pb.w,
                           pc.x, pc.y, pc.z, pc.w,  pd.x, pd.y, pd.z, pd.w};
            unsigned long long mp[8];
            #pragma unroll
            for (int q = 0; q < 8; q++) PACK2(mp[q], M[2 * q], M[2 * q + 1]);
            float N[16];
            #pragma unroll
            for (int jj = 0; jj < 16; jj++) {
                const ulonglong2* e2 = (const ulonglong2*)(Esh + jj * 16);
                ulonglong2 ea = e2[0], eb = e2[1], ec = e2[2], ed = e2[3];
                unsigned long long a0, a1;
                MUL2(a0, mp[0], ea.x);
                FMA2(a0, mp[1], ea.y, a0);
                FMA2(a0, mp[2], eb.x, a0);
                FMA2(a0, mp[3], eb.y, a0);
                MUL2(a1, mp[4], ec.x);
                FMA2(a1, mp[5], ec.y, a1);
                FMA2(a1, mp[6], ed.x, a1);
                FMA2(a1, mp[7], ed.y, a1);
                ADD2(a0, a0, a1);
                float2 f = unpack2(a0);
                N[jj] = (f.x + f.y) * p[jj];
            }
            #pragma unroll
            for (int jj = 0; jj < 16; jj++) M[jj] = N[jj];
        }
    }

    // Store TRANSPOSED: g_M[m*256 + j*16 + i] = M[i][j]; lane holds row i=li.
    float* out = g_M + (size_t)m * 256 + li;
    #pragma unroll
    for (int jj = 0; jj < 16; jj++) out[jj * 16] = M[jj];
}

// ---------------------------------------------------------------------------
// Kernel 3: combine — 32 serial mat-vecs per batch + lens + scores.
// One warp per batch.  alpha kept REPLICATED in all lanes (no broadcast shfls);
// lane j computes new alpha_j from its contiguous (transposed) column, result
// re-replicated via one SMEM round-trip.  Next chunk's column prefetched.
// ---------------------------------------------------------------------------
__global__ void __launch_bounds__(32) combine_kernel(const int*   __restrict__ text,
                                                     const int*   __restrict__ tags,
                                                     const float* __restrict__ probs,
                                                     const float* __restrict__ trans,
                                                     float*       __restrict__ out_lens,
                                                     float*       __restrict__ out_ll) {
    __shared__ float sA[16];

    int b    = blockIdx.x;
    int lane = threadIdx.x;
    int j    = lane & 15;

    // lens
    const int4* tx4 = (const int4*)(text + b * S_);
    int cnt = 0;
    #pragma unroll
    for (int q = 0; q < 4; q++) {
        int4 v = tx4[lane + q * 32];
        cnt += (v.x != 0) + (v.y != 0) + (v.z != 0) + (v.w != 0);
    }
    #pragma unroll
    for (int o = 16; o; o >>= 1) cnt += __shfl_xor_sync(FULL_, cnt, o);
    int len = cnt;
    if (lane == 0) out_lens[b] = (float)len;

    const float* pb = probs + (size_t)b * S_ * T_;

    // alpha0 replicated in every lane
    float a[16];
    {
        const float4* p4 = (const float4*)pb;
        #pragma unroll
        for (int q = 0; q < 4; q++) {
            float4 v = p4[q];
            a[4 * q + 0] = v.x; a[4 * q + 1] = v.y;
            a[4 * q + 2] = v.z; a[4 * q + 3] = v.w;
        }
    }
    float mx = a[0];
    #pragma unroll
    for (int i = 1; i < 16; i++) mx = fmaxf(mx, a[i]);
    float L = mx;
    #pragma unroll
    for (int i = 0; i < 16; i++) a[i] = __expf(a[i] - mx);

    const ulonglong2* MT = (const ulonglong2*)(g_M + (size_t)b * C_ * 256);
    ulonglong2 mc[4];
    #pragma unroll
    for (int q = 0; q < 4; q++) mc[q] = MT[j * 4 + q];   // chunk 0 column j

    #pragma unroll 1
    for (int c = 0; c < C_; c++) {
        ulonglong2 mn[4];
        if (c + 1 < C_) {
            #pragma unroll
            for (int q = 0; q < 4; q++) mn[q] = MT[(c + 1) * 64 + j * 4 + q];
        }
        int t0 = (c == 0) ? 1 : c * CS_;
        int hi = c * CS_ + CS_ - 1;
        int te = (len - 1 < hi) ? len - 1 : hi;
        int n  = te - t0 + 1;
        if (n > 0) {
            unsigned long long ap[8];
            #pragma unroll
            for (int q = 0; q < 8; q++) PACK2(ap[q], a[2 * q], a[2 * q + 1]);
            unsigned long long a0, a1;
            MUL2(a0, ap[0], mc[0].x);
            FMA2(a0, ap[1], mc[0].y, a0);
            FMA2(a0, ap[2], mc[1].x, a0);
            FMA2(a0, ap[3], mc[1].y, a0);
            MUL2(a1, ap[4], mc[2].x);
            FMA2(a1, ap[5], mc[2].y, a1);
            FMA2(a1, ap[6], mc[3].x, a1);
            FMA2(a1, ap[7], mc[3].y, a1);
            ADD2(a0, a0, a1);
            float2 f = unpack2(a0);
            float na = f.x + f.y;
            if (lane < 16) sA[j] = na;
            __syncwarp();
            {
                const float4* s4 = (const float4*)sA;
                #pragma unroll
                for (int q = 0; q < 4; q++) {
                    float4 v = s4[q];
                    a[4 * q + 0] = v.x; a[4 * q + 1] = v.y;
                    a[4 * q + 2] = v.z; a[4 * q + 3] = v.w;
                }
            }
            __syncwarp();
            float mm = a[0];
            #pragma unroll
            for (int i = 1; i < 16; i++) mm = fmaxf(mm, a[i]);
            float r = __frcp_rn(mm);
            #pragma unroll
            for (int i = 0; i < 16; i++) a[i] *= r;
            L += __logf(mm) + (float)n * LN16_;
        }
        #pragma unroll
        for (int q = 0; q < 4; q++) mc[q] = mn[q];
    }

    float ssum = 0.f;
    #pragma unroll
    for (int i = 0; i < 16; i++) ssum += a[i];
    float log_norm = L + __logf(ssum);

    // unary + binary scores
    const int* tg = tags + b * S_;
    float sc = 0.f;
    for (int s = lane; s < S_; s += 32) {
        if (s < len) {
            int t = tg[s];
            sc += pb[s * T_ + t];
            if (s >= 1) sc += trans[tg[s - 1] * T_ + t];
        }
    }
    #pragma unroll
    for (int o = 16; o; o >>= 1) sc += __shfl_xor_sync(FULL_, sc, o);

    if (lane == 0) out_ll[b] = sc - log_norm;
}

// ---------------------------------------------------------------------------
// Launch.  Output layout: probs [0,524288) | lens [524288,524352) | ll [...)
// ---------------------------------------------------------------------------
extern "C" void kernel_launch(void* const* d_in, const int* in_sizes, int n_in,
                              void* d_out, int out_size) {
    const int*   text  = (const int*)  d_in[0];
    const int*   tags  = (const int*)  d_in[1];
    const float* embed = (const float*)d_in[2];
    const float* W     = (const float*)d_in[3];
    const float* bias  = (const float*)d_in[4];
    const float* trans = (const float*)d_in[5];

    float* out      = (float*)d_out;
    float* probs    = out;
    float* out_lens = out + B_ * S_ * T_;
    float* out_ll   = out_lens + B_;

    probs_kernel  <<<(B_ * S_) / 128, 256>>>(text, embed, W, bias, probs);
    chunk_kernel  <<<(B_ * C_) / 8, 128>>>(text, probs, trans);
    combine_kernel<<<B_, 32>>>(text, tags, probs, trans, out_lens, out_ll);
}

// round 6
// speedup vs baseline: 1.6088x; 1.1536x over previous
#include <cuda_runtime.h>

// Problem constants
#define B_      64
#define S_      512
#define EMB_    300
#define T_      16
#define K4_     75          // EMB_/4
#define C_      32          // chunks per batch
#define CS_     16          // steps per chunk
#define TILE_   64          // tokens per block in probs kernel
#define FULL_   0xffffffffu
#define LN16_   2.7725887222397811f

// Packed f32x2 helpers (ptxas will not auto-fuse; must use PTX)
#define FMA2(d, a, b, c) asm("fma.rn.f32x2 %0, %1, %2, %3;" : "=l"(d) : "l"(a), "l"(b), "l"(c))
#define MUL2(d, a, b)    asm("mul.rn.f32x2 %0, %1, %2;"     : "=l"(d) : "l"(a), "l"(b))
#define ADD2(d, a, b)    asm("add.rn.f32x2 %0, %1, %2;"     : "=l"(d) : "l"(a), "l"(b))
#define PACK2(d, lo, hi) asm("mov.b64 %0, {%1, %2};"        : "=l"(d) : "f"(lo), "f"(hi))

__device__ __forceinline__ float2 unpack2(unsigned long long v) {
    float2 f;
    asm("mov.b64 {%0, %1}, %2;" : "=f"(f.x), "=f"(f.y) : "l"(v));
    return f;
}

// Scratch: per-(batch,chunk) 16x16 transfer-matrix products, stored TRANSPOSED:
// g_M[m*256 + j*16 + i] = M_m[i][j]
__device__ float g_M[B_ * C_ * 256];

// ---------------------------------------------------------------------------
// Kernel 1: probs = embed[text] @ W + b.
// Block = 256 threads, 64-token tile.  Phase 1: gather 64 embed rows into
// SMEM with fully-coalesced float4 loads.  Phase 2: warp = 8 tokens as 4
// half-pairs (lanes 0-15 / 16-31), j = lane&15.  Per k-step: 1 W-LDS.128
// (conflict-free) + 4 broadcast e-LDS.128 + 8 f32x2 FMAs.
// Dynamic SMEM: esh 64*300 f32 | W4 75*16 ulonglong2 | bsh 16 | tsh 64.
// ---------------------------------------------------------------------------
__global__ void probs_kernel(const int*   __restrict__ text,
                             const float* __restrict__ embed,
                             const float* __restrict__ W,
                             const float* __restrict__ bias,
                             float*       __restrict__ probs) {
    extern __shared__ float smem[];
    float*      esh = smem;                                   // 64*300 floats
    ulonglong2* W4  = (ulonglong2*)(smem + TILE_ * EMB_);     // 75*16
    float*      bsh = (float*)(W4 + K4_ * T_);                // 16
    int*        tsh = (int*)(bsh + T_);                       // 64

    int tid = threadIdx.x;
    int tb  = blockIdx.x * TILE_;

    // token ids
    if (tid < TILE_) tsh[tid] = text[tb + tid];

    // stage W packed as float4-per-(k,j)
    {
        float* wf = (float*)W4;
        for (int idx = tid; idx < EMB_ * T_; idx += 256) {
            int d = idx / T_, j = idx - d * T_;
            wf[((d >> 2) * T_ + j) * 4 + (d & 3)] = W[idx];
        }
        if (tid < T_) bsh[tid] = bias[tid];
    }
    __syncthreads();

    // stage 64 embed rows, coalesced float4
    {
        float4* e4 = (float4*)esh;
        #pragma unroll 4
        for (int idx = tid; idx < TILE_ * K4_; idx += 256) {
            int r = idx / K4_, c = idx - r * K4_;
            const float4* src = (const float4*)(embed + (size_t)tsh[r] * EMB_);
            e4[r * K4_ + c] = src[c];
        }
    }
    __syncthreads();

    int warp = tid >> 5, lane = tid & 31;
    int half = lane >> 4, j = lane & 15;

    // row pointers for this lane's 4 tokens (pair q -> token warp*8 + 2q + half)
    const ulonglong2* ep[4];
    #pragma unroll
    for (int q = 0; q < 4; q++)
        ep[q] = (const ulonglong2*)(esh + (warp * 8 + 2 * q + half) * EMB_);

    unsigned long long acc[4];
    #pragma unroll
    for (int q = 0; q < 4; q++) acc[q] = 0ull;

    #pragma unroll 3
    for (int k = 0; k < K4_; k++) {
        ulonglong2 w = W4[k * T_ + j];
        #pragma unroll
        for (int q = 0; q < 4; q++) {
            ulonglong2 e = ep[q][k];
            FMA2(acc[q], e.x, w.x, acc[q]);
            FMA2(acc[q], e.y, w.y, acc[q]);
        }
    }

    #pragma unroll
    for (int q = 0; q < 4; q++) {
        float2 f = unpack2(acc[q]);
        int token = tb + warp * 8 + 2 * q + half;
        probs[(size_t)token * T_ + j] = f.x + f.y + bsh[j];
    }
}

// ---------------------------------------------------------------------------
// Kernel 2: per-(batch,chunk) transfer-matrix products (f32x2 mainloop).
// ---------------------------------------------------------------------------
__global__ void __launch_bounds__(128) chunk_kernel(const int*   __restrict__ text,
                                                    const float* __restrict__ probs,
                                                    const float* __restrict__ trans) {
    __shared__ float Esh[256];       // Esh[j*16+k] = exp(trans[k][j])
    __shared__ float psh[4][512];    // per warp: [half*256 + dt*16 + j]

    int tid = threadIdx.x;
    for (int idx = tid; idx < 256; idx += 128) {
        int k = idx >> 4, jj = idx & 15;
        Esh[jj * 16 + k] = __expf(trans[idx]);
    }

    int warp = tid >> 5, lane = tid & 31;
    int half = lane >> 4, li = lane & 15;
    int m = blockIdx.x * 8 + warp * 2 + half;
    int b = m >> 5, c = m & (C_ - 1);

    // len for batch b
    const int4* tx4 = (const int4*)(text + b * S_);
    int cnt = 0;
    #pragma unroll
    for (int q = 0; q < 8; q++) {
        int4 v = tx4[li + q * 16];
        cnt += (v.x != 0) + (v.y != 0) + (v.z != 0) + (v.w != 0);
    }
    #pragma unroll
    for (int o = 8; o; o >>= 1) cnt += __shfl_xor_sync(FULL_, cnt, o);
    int len = cnt;

    // Stage exp(emit)/16 for this chunk's 16 steps
    {
        const float4* p4 = (const float4*)(probs + ((size_t)b * S_ + c * CS_) * T_);
        float* myp = &psh[warp][half * 256];
        #pragma unroll
        for (int q = 0; q < 4; q++) {
            float4 v = p4[li + q * 16];
            int o4 = (li + q * 16) * 4;
            myp[o4 + 0] = __expf(v.x) * 0.0625f;
            myp[o4 + 1] = __expf(v.y) * 0.0625f;
            myp[o4 + 2] = __expf(v.z) * 0.0625f;
            myp[o4 + 3] = __expf(v.w) * 0.0625f;
        }
    }
    __syncthreads();

    float M[16];
    #pragma unroll
    for (int jj = 0; jj < 16; jj++) M[jj] = (jj == li) ? 1.f : 0.f;

    const float* myp = &psh[warp][half * 256];
    #pragma unroll 1
    for (int dt = 0; dt < CS_; dt++) {
        int t = c * CS_ + dt;
        if (t >= 1 && t < len) {
            const float4* pv = (const float4*)(myp + dt * 16);
            float4 pa = pv[0], pb = pv[1], pc = pv[2], pd = pv[3];
            float p[16] = {pa.x, pa.y, pa.z, pa.w,  pb.x, pb.y, pb.z, pb.w,
                           pc.x, pc.y, pc.z, pc.w,  pd.x, pd.y, pd.z, pd.w};
            unsigned long long mp[8];
            #pragma unroll
            for (int q = 0; q < 8; q++) PACK2(mp[q], M[2 * q], M[2 * q + 1]);
            float N[16];
            #pragma unroll
            for (int jj = 0; jj < 16; jj++) {
                const ulonglong2* e2 = (const ulonglong2*)(Esh + jj * 16);
                ulonglong2 ea = e2[0], eb = e2[1], ec = e2[2], ed = e2[3];
                unsigned long long a0, a1;
                MUL2(a0, mp[0], ea.x);
                FMA2(a0, mp[1], ea.y, a0);
                FMA2(a0, mp[2], eb.x, a0);
                FMA2(a0, mp[3], eb.y, a0);
                MUL2(a1, mp[4], ec.x);
                FMA2(a1, mp[5], ec.y, a1);
                FMA2(a1, mp[6], ed.x, a1);
                FMA2(a1, mp[7], ed.y, a1);
                ADD2(a0, a0, a1);
                float2 f = unpack2(a0);
                N[jj] = (f.x + f.y) * p[jj];
            }
            #pragma unroll
            for (int jj = 0; jj < 16; jj++) M[jj] = N[jj];
        }
    }

    // Store TRANSPOSED: g_M[m*256 + j*16 + i] = M[i][j]; lane holds row i=li.
    float* out = g_M + (size_t)m * 256 + li;
    #pragma unroll
    for (int jj = 0; jj < 16; jj++) out[jj * 16] = M[jj];
}

// ---------------------------------------------------------------------------
// Kernel 3: combine — 32 serial mat-vecs per batch + lens + scores.
// alpha replicated in all lanes; transposed matrices give contiguous columns.
// ---------------------------------------------------------------------------
__global__ void __launch_bounds__(32) combine_kernel(const int*   __restrict__ text,
                                                     const int*   __restrict__ tags,
                                                     const float* __restrict__ probs,
                                                     const float* __restrict__ trans,
                                                     float*       __restrict__ out_lens,
                                                     float*       __restrict__ out_ll) {
    __shared__ float sA[16];

    int b    = blockIdx.x;
    int lane = threadIdx.x;
    int j    = lane & 15;

    // lens
    const int4* tx4 = (const int4*)(text + b * S_);
    int cnt = 0;
    #pragma unroll
    for (int q = 0; q < 4; q++) {
        int4 v = tx4[lane + q * 32];
        cnt += (v.x != 0) + (v.y != 0) + (v.z != 0) + (v.w != 0);
    }
    #pragma unroll
    for (int o = 16; o; o >>= 1) cnt += __shfl_xor_sync(FULL_, cnt, o);
    int len = cnt;
    if (lane == 0) out_lens[b] = (float)len;

    const float* pb = probs + (size_t)b * S_ * T_;

    // alpha0 replicated in every lane
    float a[16];
    {
        const float4* p4 = (const float4*)pb;
        #pragma unroll
        for (int q = 0; q < 4; q++) {
            float4 v = p4[q];
            a[4 * q + 0] = v.x; a[4 * q + 1] = v.y;
            a[4 * q + 2] = v.z; a[4 * q + 3] = v.w;
        }
    }
    float mx = a[0];
    #pragma unroll
    for (int i = 1; i < 16; i++) mx = fmaxf(mx, a[i]);
    float L = mx;
    #pragma unroll
    for (int i = 0; i < 16; i++) a[i] = __expf(a[i] - mx);

    const ulonglong2* MT = (const ulonglong2*)(g_M + (size_t)b * C_ * 256);
    ulonglong2 mc[4];
    #pragma unroll
    for (int q = 0; q < 4; q++) mc[q] = MT[j * 4 + q];   // chunk 0 column j

    #pragma unroll 1
    for (int c = 0; c < C_; c++) {
        ulonglong2 mn[4];
        if (c + 1 < C_) {
            #pragma unroll
            for (int q = 0; q < 4; q++) mn[q] = MT[(c + 1) * 64 + j * 4 + q];
        }
        int t0 = (c == 0) ? 1 : c * CS_;
        int hi = c * CS_ + CS_ - 1;
        int te = (len - 1 < hi) ? len - 1 : hi;
        int n  = te - t0 + 1;
        if (n > 0) {
            unsigned long long ap[8];
            #pragma unroll
            for (int q = 0; q < 8; q++) PACK2(ap[q], a[2 * q], a[2 * q + 1]);
            unsigned long long a0, a1;
            MUL2(a0, ap[0], mc[0].x);
            FMA2(a0, ap[1], mc[0].y, a0);
            FMA2(a0, ap[2], mc[1].x, a0);
            FMA2(a0, ap[3], mc[1].y, a0);
            MUL2(a1, ap[4], mc[2].x);
            FMA2(a1, ap[5], mc[2].y, a1);
            FMA2(a1, ap[6], mc[3].x, a1);
            FMA2(a1, ap[7], mc[3].y, a1);
            ADD2(a0, a0, a1);
            float2 f = unpack2(a0);
            float na = f.x + f.y;
            if (lane < 16) sA[j] = na;
            __syncwarp();
            {
                const float4* s4 = (const float4*)sA;
                #pragma unroll
                for (int q = 0; q < 4; q++) {
                    float4 v = s4[q];
                    a[4 * q + 0] = v.x; a[4 * q + 1] = v.y;
                    a[4 * q + 2] = v.z; a[4 * q + 3] = v.w;
                }
            }
            __syncwarp();
            float mm = a[0];
            #pragma unroll
            for (int i = 1; i < 16; i++) mm = fmaxf(mm, a[i]);
            float r = __frcp_rn(mm);
            #pragma unroll
            for (int i = 0; i < 16; i++) a[i] *= r;
            L += __logf(mm) + (float)n * LN16_;
        }
        #pragma unroll
        for (int q = 0; q < 4; q++) mc[q] = mn[q];
    }

    float ssum = 0.f;
    #pragma unroll
    for (int i = 0; i < 16; i++) ssum += a[i];
    float log_norm = L + __logf(ssum);

    // unary + binary scores
    const int* tg = tags + b * S_;
    float sc = 0.f;
    for (int s = lane; s < S_; s += 32) {
        if (s < len) {
            int t = tg[s];
            sc += pb[s * T_ + t];
            if (s >= 1) sc += trans[tg[s - 1] * T_ + t];
        }
    }
    #pragma unroll
    for (int o = 16; o; o >>= 1) sc += __shfl_xor_sync(FULL_, sc, o);

    if (lane == 0) out_ll[b] = sc - log_norm;
}

// ---------------------------------------------------------------------------
// Launch.  Output layout: probs [0,524288) | lens [524288,524352) | ll [...)
// ---------------------------------------------------------------------------
extern "C" void kernel_launch(void* const* d_in, const int* in_sizes, int n_in,
                              void* d_out, int out_size) {
    const int*   text  = (const int*)  d_in[0];
    const int*   tags  = (const int*)  d_in[1];
    const float* embed = (const float*)d_in[2];
    const float* W     = (const float*)d_in[3];
    const float* bias  = (const float*)d_in[4];
    const float* trans = (const float*)d_in[5];

    float* out      = (float*)d_out;
    float* probs    = out;
    float* out_lens = out + B_ * S_ * T_;
    float* out_ll   = out_lens + B_;

    // dynamic SMEM for probs: esh + W4 + bsh + tsh
    int smem_bytes = TILE_ * EMB_ * 4 + K4_ * T_ * 16 + T_ * 4 + TILE_ * 4;
    cudaFuncSetAttribute(probs_kernel,
                         cudaFuncAttributeMaxDynamicSharedMemorySize, smem_bytes);

    probs_kernel  <<<(B_ * S_) / TILE_, 256, smem_bytes>>>(text, embed, W, bias, probs);
    chunk_kernel  <<<(B_ * C_) / 8, 128>>>(text, probs, trans);
    combine_kernel<<<B_, 32>>>(text, tags, probs, trans, out_lens, out_ll);
}

// round 8
// speedup vs baseline: 1.6612x; 1.0325x over previous
#include <cuda_runtime.h>

// Problem constants
#define B_      64
#define S_      512
#define EMB_    300
#define T_      16
#define K4_     75          // EMB_/4
#define C_      32          // chunks per batch
#define CS_     16          // steps per chunk
#define TILE_   64          // tokens per block in probs kernel
#define FULL_   0xffffffffu
#define LN16_   2.7725887222397811f

// Packed f32x2 helpers (ptxas will not auto-fuse; must use PTX)
#define FMA2(d, a, b, c) asm("fma.rn.f32x2 %0, %1, %2, %3;" : "=l"(d) : "l"(a), "l"(b), "l"(c))
#define MUL2(d, a, b)    asm("mul.rn.f32x2 %0, %1, %2;"     : "=l"(d) : "l"(a), "l"(b))
#define ADD2(d, a, b)    asm("add.rn.f32x2 %0, %1, %2;"     : "=l"(d) : "l"(a), "l"(b))
#define PACK2(d, lo, hi) asm("mov.b64 %0, {%1, %2};"        : "=l"(d) : "f"(lo), "f"(hi))

__device__ __forceinline__ float2 unpack2(unsigned long long v) {
    float2 f;
    asm("mov.b64 {%0, %1}, %2;" : "=f"(f.x), "=f"(f.y) : "l"(v));
    return f;
}

// Scratch: per-(batch,chunk) 16x16 transfer-matrix products, stored TRANSPOSED:
// g_M[m*256 + j*16 + i] = M_m[i][j]
__device__ float g_M[B_ * C_ * 256];

// ---------------------------------------------------------------------------
// Kernel 1: probs = embed[text] @ W + b.
// Block = 256 threads, 64-token tile.
// Phase 1: gather 64 embed rows into SMEM, 4 threads per row, unrolled (MLP).
// Phase 2: warp = 8 tokens as 4 half-pairs, j = lane&15.  Inner loop is
// SOFTWARE-PIPELINED: iteration k+1's 5 LDS.128 issue before iteration k's
// 16 FMA2 consume — LDS latency (29cyc) hidden behind the FMA block.
// W4 has one pad row so the k=75 prefetch is branchless and in-bounds.
// ---------------------------------------------------------------------------
__global__ void probs_kernel(const int*   __restrict__ text,
                             const float* __restrict__ embed,
                             const float* __restrict__ W,
                             const float* __restrict__ bias,
                             float*       __restrict__ probs) {
    extern __shared__ float smem[];
    float*      esh = smem;                                    // 64*300 floats
    ulonglong2* W4  = (ulonglong2*)(smem + TILE_ * EMB_);      // (75+1)*16
    float*      bsh = (float*)(W4 + (K4_ + 1) * T_);           // 16
    int*        tsh = (int*)(bsh + T_);                        // 64

    int tid = threadIdx.x;
    int tb  = blockIdx.x * TILE_;

    if (tid < TILE_) tsh[tid] = text[tb + tid];

    // stage W packed as float4-per-(k,j)
    {
        float* wf = (float*)W4;
        for (int idx = tid; idx < EMB_ * T_; idx += 256) {
            int d = idx / T_, j = idx - d * T_;
            wf[((d >> 2) * T_ + j) * 4 + (d & 3)] = W[idx];
        }
        if (tid < T_) bsh[tid] = bias[tid];
    }
    __syncthreads();

    // stage 64 embed rows: 4 threads per row, 19 unrolled steps
    {
        int r  = tid >> 2, c0 = tid & 3;
        const float4* src = (const float4*)(embed + (size_t)tsh[r] * EMB_);
        float4*       dst = (float4*)(esh + r * EMB_);
        #pragma unroll
        for (int q = 0; q < 19; q++) {
            int c = c0 + 4 * q;
            if (c < K4_) dst[c] = src[c];
        }
    }
    __syncthreads();

    int warp = tid >> 5, lane = tid & 31;
    int half = lane >> 4, j = lane & 15;

    const ulonglong2* ep0 = (const ulonglong2*)(esh + (warp * 8 + 0 + half) * EMB_);
    const ulonglong2* ep1 = (const ulonglong2*)(esh + (warp * 8 + 2 + half) * EMB_);
    const ulonglong2* ep2 = (const ulonglong2*)(esh + (warp * 8 + 4 + half) * EMB_);
    const ulonglong2* ep3 = (const ulonglong2*)(esh + (warp * 8 + 6 + half) * EMB_);

    unsigned long long acc0 = 0ull, acc1 = 0ull, acc2 = 0ull, acc3 = 0ull;

    // pipeline prologue
    ulonglong2 w  = W4[j];
    ulonglong2 e0 = ep0[0], e1 = ep1[0], e2 = ep2[0], e3 = ep3[0];

    #pragma unroll 5
    for (int k = 0; k < K4_; k++) {
        // prefetch k+1 (k=74 reads pad row / adjacent SMEM, never consumed)
        ulonglong2 wn  = W4[(k + 1) * T_ + j];
        ulonglong2 en0 = ep0[k + 1];
        ulonglong2 en1 = ep1[k + 1];
        ulonglong2 en2 = ep2[k + 1];
        ulonglong2 en3 = ep3[k + 1];

        FMA2(acc0, e0.x, w.x, acc0);
        FMA2(acc1, e1.x, w.x, acc1);
        FMA2(acc2, e2.x, w.x, acc2);
        FMA2(acc3, e3.x, w.x, acc3);
        FMA2(acc0, e0.y, w.y, acc0);
        FMA2(acc1, e1.y, w.y, acc1);
        FMA2(acc2, e2.y, w.y, acc2);
        FMA2(acc3, e3.y, w.y, acc3);

        w = wn; e0 = en0; e1 = en1; e2 = en2; e3 = en3;
    }

    float2 f0 = unpack2(acc0);
    float2 f1 = unpack2(acc1);
    float2 f2 = unpack2(acc2);
    float2 f3 = unpack2(acc3);
    float bj = bsh[j];
    probs[(size_t)(tb + warp * 8 + 0 + half) * T_ + j] = f0.x + f0.y + bj;
    probs[(size_t)(tb + warp * 8 + 2 + half) * T_ + j] = f1.x + f1.y + bj;
    probs[(size_t)(tb + warp * 8 + 4 + half) * T_ + j] = f2.x + f2.y + bj;
    probs[(size_t)(tb + warp * 8 + 6 + half) * T_ + j] = f3.x + f3.y + bj;
}

// ---------------------------------------------------------------------------
// Kernel 2: per-(batch,chunk) transfer-matrix products (f32x2 mainloop).
// ---------------------------------------------------------------------------
__global__ void __launch_bounds__(128) chunk_kernel(const int*   __restrict__ text,
                                                    const float* __restrict__ probs,
                                                    const float* __restrict__ trans) {
    __shared__ float Esh[256];       // Esh[j*16+k] = exp(trans[k][j])
    __shared__ float psh[4][512];    // per warp: [half*256 + dt*16 + j]

    int tid = threadIdx.x;
    for (int idx = tid; idx < 256; idx += 128) {
        int k = idx >> 4, jj = idx & 15;
        Esh[jj * 16 + k] = __expf(trans[idx]);
    }

    int warp = tid >> 5, lane = tid & 31;
    int half = lane >> 4, li = lane & 15;
    int m = blockIdx.x * 8 + warp * 2 + half;
    int b = m >> 5, c = m & (C_ - 1);

    // len for batch b
    const int4* tx4 = (const int4*)(text + b * S_);
    int cnt = 0;
    #pragma unroll
    for (int q = 0; q < 8; q++) {
        int4 v = tx4[li + q * 16];
        cnt += (v.x != 0) + (v.y != 0) + (v.z != 0) + (v.w != 0);
    }
    #pragma unroll
    for (int o = 8; o; o >>= 1) cnt += __shfl_xor_sync(FULL_, cnt, o);
    int len = cnt;

    // Stage exp(emit)/16 for this chunk's 16 steps
    {
        const float4* p4 = (const float4*)(probs + ((size_t)b * S_ + c * CS_) * T_);
        float* myp = &psh[warp][half * 256];
        #pragma unroll
        for (int q = 0; q < 4; q++) {
            float4 v = p4[li + q * 16];
            int o4 = (li + q * 16) * 4;
            myp[o4 + 0] = __expf(v.x) * 0.0625f;
            myp[o4 + 1] = __expf(v.y) * 0.0625f;
            myp[o4 + 2] = __expf(v.z) * 0.0625f;
            myp[o4 + 3] = __expf(v.w) * 0.0625f;
        }
    }
    __syncthreads();

    float M[16];
    #pragma unroll
    for (int jj = 0; jj < 16; jj++) M[jj] = (jj == li) ? 1.f : 0.f;

    const float* myp = &psh[warp][half * 256];
    #pragma unroll 1
    for (int dt = 0; dt < CS_; dt++) {
        int t = c * CS_ + dt;
        if (t >= 1 && t < len) {
            const float4* pv = (const float4*)(myp + dt * 16);
            float4 pa = pv[0], pb = pv[1], pc = pv[2], pd = pv[3];
            float p[16] = {pa.x, pa.y, pa.z, pa.w,  pb.x, pb.y, pb.z, pb.w,
                           pc.x, pc.y, pc.z, pc.w,  pd.x, pd.y, pd.z, pd.w};
            unsigned long long mp[8];
            #pragma unroll
            for (int q = 0; q < 8; q++) PACK2(mp[q], M[2 * q], M[2 * q + 1]);
            float N[16];
            #pragma unroll
            for (int jj = 0; jj < 16; jj++) {
                const ulonglong2* e2 = (const ulonglong2*)(Esh + jj * 16);
                ulonglong2 ea = e2[0], eb = e2[1], ec = e2[2], ed = e2[3];
                unsigned long long a0, a1;
                MUL2(a0, mp[0], ea.x);
                FMA2(a0, mp[1], ea.y, a0);
                FMA2(a0, mp[2], eb.x, a0);
                FMA2(a0, mp[3], eb.y, a0);
                MUL2(a1, mp[4], ec.x);
                FMA2(a1, mp[5], ec.y, a1);
                FMA2(a1, mp[6], ed.x, a1);
                FMA2(a1, mp[7], ed.y, a1);
                ADD2(a0, a0, a1);
                float2 f = unpack2(a0);
                N[jj] = (f.x + f.y) * p[jj];
            }
            #pragma unroll
            for (int jj = 0; jj < 16; jj++) M[jj] = N[jj];
        }
    }

    // Store TRANSPOSED: g_M[m*256 + j*16 + i] = M[i][j]; lane holds row i=li.
    float* out = g_M + (size_t)m * 256 + li;
    #pragma unroll
    for (int jj = 0; jj < 16; jj++) out[jj * 16] = M[jj];
}

// ---------------------------------------------------------------------------
// Kernel 3: combine — 32 serial mat-vecs per batch + lens + scores.
// alpha replicated in all lanes; transposed matrices give contiguous columns.
// ---------------------------------------------------------------------------
__global__ void __launch_bounds__(32) combine_kernel(const int*   __restrict__ text,
                                                     const int*   __restrict__ tags,
                                                     const float* __restrict__ probs,
                                                     const float* __restrict__ trans,
                                                     float*       __restrict__ out_lens,
                                                     float*       __restrict__ out_ll) {
    __shared__ float sA[16];

    int b    = blockIdx.x;
    int lane = threadIdx.x;
    int j    = lane & 15;

    // lens
    const int4* tx4 = (const int4*)(text + b * S_);
    int cnt = 0;
    #pragma unroll
    for (int q = 0; q < 4; q++) {
        int4 v = tx4[lane + q * 32];
        cnt += (v.x != 0) + (v.y != 0) + (v.z != 0) + (v.w != 0);
    }
    #pragma unroll
    for (int o = 16; o; o >>= 1) cnt += __shfl_xor_sync(FULL_, cnt, o);
    int len = cnt;
    if (lane == 0) out_lens[b] = (float)len;

    const float* pb = probs + (size_t)b * S_ * T_;

    // alpha0 replicated in every lane
    float a[16];
    {
        const float4* p4 = (const float4*)pb;
        #pragma unroll
        for (int q = 0; q < 4; q++) {
            float4 v = p4[q];
            a[4 * q + 0] = v.x; a[4 * q + 1] = v.y;
            a[4 * q + 2] = v.z; a[4 * q + 3] = v.w;
        }
    }
    float mx = a[0];
    #pragma unroll
    for (int i = 1; i < 16; i++) mx = fmaxf(mx, a[i]);
    float L = mx;
    #pragma unroll
    for (int i = 0; i < 16; i++) a[i] = __expf(a[i] - mx);

    const ulonglong2* MT = (const ulonglong2*)(g_M + (size_t)b * C_ * 256);
    ulonglong2 mc[4];
    #pragma unroll
    for (int q = 0; q < 4; q++) mc[q] = MT[j * 4 + q];   // chunk 0 column j

    #pragma unroll 1
    for (int c = 0; c < C_; c++) {
        ulonglong2 mn[4];
        if (c + 1 < C_) {
            #pragma unroll
            for (int q = 0; q < 4; q++) mn[q] = MT[(c + 1) * 64 + j * 4 + q];
        }
        int t0 = (c == 0) ? 1 : c * CS_;
        int hi = c * CS_ + CS_ - 1;
        int te = (len - 1 < hi) ? len - 1 : hi;
        int n  = te - t0 + 1;
        if (n > 0) {
            unsigned long long ap[8];
            #pragma unroll
            for (int q = 0; q < 8; q++) PACK2(ap[q], a[2 * q], a[2 * q + 1]);
            unsigned long long a0, a1;
            MUL2(a0, ap[0], mc[0].x);
            FMA2(a0, ap[1], mc[0].y, a0);
            FMA2(a0, ap[2], mc[1].x, a0);
            FMA2(a0, ap[3], mc[1].y, a0);
            MUL2(a1, ap[4], mc[2].x);
            FMA2(a1, ap[5], mc[2].y, a1);
            FMA2(a1, ap[6], mc[3].x, a1);
            FMA2(a1, ap[7], mc[3].y, a1);
            ADD2(a0, a0, a1);
            float2 f = unpack2(a0);
            float na = f.x + f.y;
            if (lane < 16) sA[j] = na;
            __syncwarp();
            {
                const float4* s4 = (const float4*)sA;
                #pragma unroll
                for (int q = 0; q < 4; q++) {
                    float4 v = s4[q];
                    a[4 * q + 0] = v.x; a[4 * q + 1] = v.y;
                    a[4 * q + 2] = v.z; a[4 * q + 3] = v.w;
                }
            }
            __syncwarp();
            float mm = a[0];
            #pragma unroll
            for (int i = 1; i < 16; i++) mm = fmaxf(mm, a[i]);
            float r = __frcp_rn(mm);
            #pragma unroll
            for (int i = 0; i < 16; i++) a[i] *= r;
            L += __logf(mm) + (float)n * LN16_;
        }
        #pragma unroll
        for (int q = 0; q < 4; q++) mc[q] = mn[q];
    }

    float ssum = 0.f;
    #pragma unroll
    for (int i = 0; i < 16; i++) ssum += a[i];
    float log_norm = L + __logf(ssum);

    // unary + binary scores
    const int* tg = tags + b * S_;
    float sc = 0.f;
    for (int s = lane; s < S_; s += 32) {
        if (s < len) {
            int t = tg[s];
            sc += pb[s * T_ + t];
            if (s >= 1) sc += trans[tg[s - 1] * T_ + t];
        }
    }
    #pragma unroll
    for (int o = 16; o; o >>= 1) sc += __shfl_xor_sync(FULL_, sc, o);

    if (lane == 0) out_ll[b] = sc - log_norm;
}

// ---------------------------------------------------------------------------
// Launch.  Output layout: probs [0,524288) | lens [524288,524352) | ll [...)
// ---------------------------------------------------------------------------
extern "C" void kernel_launch(void* const* d_in, const int* in_sizes, int n_in,
                              void* d_out, int out_size) {
    const int*   text  = (const int*)  d_in[0];
    const int*   tags  = (const int*)  d_in[1];
    const float* embed = (const float*)d_in[2];
    const float* W     = (const float*)d_in[3];
    const float* bias  = (const float*)d_in[4];
    const float* trans = (const float*)d_in[5];

    float* out      = (float*)d_out;
    float* probs    = out;
    float* out_lens = out + B_ * S_ * T_;
    float* out_ll   = out_lens + B_;

    // dynamic SMEM for probs: esh + W4 (with pad row) + bsh + tsh
    int smem_bytes = TILE_ * EMB_ * 4 + (K4_ + 1) * T_ * 16 + T_ * 4 + TILE_ * 4;
    cudaFuncSetAttribute(probs_kernel,
                         cudaFuncAttributeMaxDynamicSharedMemorySize, smem_bytes);

    probs_kernel  <<<(B_ * S_) / TILE_, 256, smem_bytes>>>(text, embed, W, bias, probs);
    chunk_kernel  <<<(B_ * C_) / 8, 128>>>(text, probs, trans);
    combine_kernel<<<B_, 32>>>(text, tags, probs, trans, out_lens, out_ll);
}

// round 10
// speedup vs baseline: 1.8654x; 1.1230x over previous
#include <cuda_runtime.h>

// Problem constants
#define B_      64
#define S_      512
#define EMB_    300
#define T_      16
#define K4_     75          // EMB_/4
#define KSPLIT_ 38          // k4 split point: warps 0-7 do [0,38), 8-15 do [38,75)
#define C_      32          // chunks per batch
#define CS_     16          // steps per chunk
#define TILE_   64          // tokens per block in probs kernel
#define FULL_   0xffffffffu
#define LN16_   2.7725887222397811f

// Packed f32x2 helpers
#define FMA2(d, a, b, c) asm("fma.rn.f32x2 %0, %1, %2, %3;" : "=l"(d) : "l"(a), "l"(b), "l"(c))
#define MUL2(d, a, b)    asm("mul.rn.f32x2 %0, %1, %2;"     : "=l"(d) : "l"(a), "l"(b), "l"(c))
#define MUL2b(d, a, b)   asm("mul.rn.f32x2 %0, %1, %2;"     : "=l"(d) : "l"(a), "l"(b))
#define ADD2(d, a, b)    asm("add.rn.f32x2 %0, %1, %2;"     : "=l"(d) : "l"(a), "l"(b))
#define PACK2(d, lo, hi) asm("mov.b64 %0, {%1, %2};"        : "=l"(d) : "f"(lo), "f"(hi))

__device__ __forceinline__ float2 unpack2(unsigned long long v) {
    float2 f;
    asm("mov.b64 {%0, %1}, %2;" : "=f"(f.x), "=f"(f.y) : "l"(v));
    return f;
}

// ---------------------------------------------------------------------------
// Kernel 1: probs = embed[text] @ W + b.   512 threads, 64-token tile,
// K-SPLIT across warp halves: warps 0-7 accumulate k4 in [0,38), warps 8-15
// in [38,75); partials merged via SMEM.  Doubles resident warps per SM at
// the same SMEM footprint and halves each warp's serial loop.
// ---------------------------------------------------------------------------
__global__ void __launch_bounds__(512) probs_kernel(const int*   __restrict__ text,
                                                    const float* __restrict__ embed,
                                                    const float* __restrict__ W,
                                                    const float* __restrict__ bias,
                                                    float*       __restrict__ probs) {
    extern __shared__ float smem[];
    float*      esh  = smem;                                   // 64*300
    ulonglong2* W4   = (ulonglong2*)(smem + TILE_ * EMB_);     // (75+1)*16
    float*      bsh  = (float*)(W4 + (K4_ + 1) * T_);          // 16
    int*        tsh  = (int*)(bsh + T_);                       // 64
    float*      part = (float*)(tsh + TILE_);                  // 64*16

    int tid = threadIdx.x;
    int tb  = blockIdx.x * TILE_;

    if (tid < TILE_) tsh[tid] = text[tb + tid];

    // stage W packed as float4-per-(k,j)
    {
        float* wf = (float*)W4;
        for (int idx = tid; idx < EMB_ * T_; idx += 512) {
            int d = idx / T_, j = idx - d * T_;
            wf[((d >> 2) * T_ + j) * 4 + (d & 3)] = W[idx];
        }
        if (tid < T_) bsh[tid] = bias[tid];
    }
    __syncthreads();

    // stage 64 embed rows: 8 threads per row
    {
        int r  = tid >> 3, c0 = tid & 7;
        const float4* src = (const float4*)(embed + (size_t)tsh[r] * EMB_);
        float4*       dst = (float4*)(esh + r * EMB_);
        #pragma unroll
        for (int q = 0; q < 10; q++) {
            int c = c0 + 8 * q;
            if (c < K4_) dst[c] = src[c];
        }
    }
    __syncthreads();

    int warp = tid >> 5, lane = tid & 31;
    int h    = warp >> 3;            // K-half
    int wl   = warp & 7;
    int half = lane >> 4, j = lane & 15;
    int kb   = h ? KSPLIT_ : 0;
    int ke   = h ? K4_ : KSPLIT_;

    int t0 = wl * 8 + 0 + half;
    int t1 = wl * 8 + 2 + half;
    int t2 = wl * 8 + 4 + half;
    int t3 = wl * 8 + 6 + half;
    const ulonglong2* ep0 = (const ulonglong2*)(esh + t0 * EMB_);
    const ulonglong2* ep1 = (const ulonglong2*)(esh + t1 * EMB_);
    const ulonglong2* ep2 = (const ulonglong2*)(esh + t2 * EMB_);
    const ulonglong2* ep3 = (const ulonglong2*)(esh + t3 * EMB_);

    unsigned long long acc0 = 0ull, acc1 = 0ull, acc2 = 0ull, acc3 = 0ull;

    ulonglong2 w  = W4[kb * T_ + j];
    ulonglong2 e0 = ep0[kb], e1 = ep1[kb], e2 = ep2[kb], e3 = ep3[kb];

    #pragma unroll 2
    for (int k = kb; k < ke; k++) {
        // prefetch k+1 (bounded by pad row at k=75)
        ulonglong2 wn  = W4[(k + 1) * T_ + j];
        ulonglong2 en0 = ep0[k + 1];
        ulonglong2 en1 = ep1[k + 1];
        ulonglong2 en2 = ep2[k + 1];
        ulonglong2 en3 = ep3[k + 1];

        FMA2(acc0, e0.x, w.x, acc0);
        FMA2(acc1, e1.x, w.x, acc1);
        FMA2(acc2, e2.x, w.x, acc2);
        FMA2(acc3, e3.x, w.x, acc3);
        FMA2(acc0, e0.y, w.y, acc0);
        FMA2(acc1, e1.y, w.y, acc1);
        FMA2(acc2, e2.y, w.y, acc2);
        FMA2(acc3, e3.y, w.y, acc3);

        w = wn; e0 = en0; e1 = en1; e2 = en2; e3 = en3;
    }

    float2 f0 = unpack2(acc0);
    float2 f1 = unpack2(acc1);
    float2 f2 = unpack2(acc2);
    float2 f3 = unpack2(acc3);
    float s0 = f0.x + f0.y, s1 = f1.x + f1.y, s2 = f2.x + f2.y, s3 = f3.x + f3.y;

    if (h == 1) {
        part[t0 * T_ + j] = s0;
        part[t1 * T_ + j] = s1;
        part[t2 * T_ + j] = s2;
        part[t3 * T_ + j] = s3;
    }
    __syncthreads();
    if (h == 0) {
        float bj = bsh[j];
        probs[(size_t)(tb + t0) * T_ + j] = s0 + part[t0 * T_ + j] + bj;
        probs[(size_t)(tb + t1) * T_ + j] = s1 + part[t1 * T_ + j] + bj;
        probs[(size_t)(tb + t2) * T_ + j] = s2 + part[t2 * T_ + j] + bj;
        probs[(size_t)(tb + t3) * T_ + j] = s3 + part[t3 * T_ + j] + bj;
    }
}

// ---------------------------------------------------------------------------
// Kernel 2: fused CRF.  One block (512 thr, 16 warps) per batch row.
// Phase A: 16 warps build the 32 per-chunk transfer matrices (half-warp per
//          chunk) into SMEM (transposed).
// Phase B: warp 0 runs the 32 serial mat-vecs from SMEM (LDS latency) while
//          warps 1-15 compute unary+binary scores in parallel.
// ---------------------------------------------------------------------------
__global__ void __launch_bounds__(512) crf_kernel(const int*   __restrict__ text,
                                                  const int*   __restrict__ tags,
                                                  const float* __restrict__ probs,
                                                  const float* __restrict__ trans,
                                                  float*       __restrict__ out_lens,
                                                  float*       __restrict__ out_ll) {
    extern __shared__ float smem[];
    float* Msh = smem;                      // 32 chunks * 256 (transposed)
    float* psh = Msh + C_ * 256;            // 16 warps * 512
    float* Esh = psh + 16 * 512;            // 256
    float* sA  = Esh + 256;                 // 16
    float* scp = sA + 16;                   // 16 (score partials)
    int*   cnt = (int*)(scp + 16);          // 16

    int tid  = threadIdx.x;
    int warp = tid >> 5, lane = tid & 31;
    int b    = blockIdx.x;

    // Esh[j*16+k] = exp(trans[k][j])
    if (tid < 256) {
        int k = tid >> 4, jj = tid & 15;
        Esh[jj * 16 + k] = __expf(trans[tid]);
    }

    // len via ballot: thread s tests text[b][s]
    {
        int nz = (text[b * S_ + tid] != 0);
        unsigned bal = __ballot_sync(FULL_, nz);
        if (lane == 0) cnt[warp] = __popc(bal);
    }
    __syncthreads();
    int len = 0;
    #pragma unroll
    for (int q = 0; q < 16; q++) len += cnt[q];

    int half = lane >> 4, li = lane & 15;
    int c = warp * 2 + half;               // chunk id

    // Stage exp(emit)/16 for this chunk's 16 steps (own half-warp only)
    {
        const float4* p4 = (const float4*)(probs + ((size_t)b * S_ + c * CS_) * T_);
        float* myp = psh + warp * 512 + half * 256;
        #pragma unroll
        for (int q = 0; q < 4; q++) {
            float4 v = p4[li + q * 16];
            int o4 = (li + q * 16) * 4;
            myp[o4 + 0] = __expf(v.x) * 0.0625f;
            myp[o4 + 1] = __expf(v.y) * 0.0625f;
            myp[o4 + 2] = __expf(v.z) * 0.0625f;
            myp[o4 + 3] = __expf(v.w) * 0.0625f;
        }
    }
    __syncwarp();

    // Build chunk matrix: lane li = row
    float M[16];
    #pragma unroll
    for (int jj = 0; jj < 16; jj++) M[jj] = (jj == li) ? 1.f : 0.f;

    const float* myp = psh + warp * 512 + half * 256;
    #pragma unroll 1
    for (int dt = 0; dt < CS_; dt++) {
        int t = c * CS_ + dt;
        if (t >= 1 && t < len) {
            const float4* pv = (const float4*)(myp + dt * 16);
            float4 pa = pv[0], pb = pv[1], pc = pv[2], pd = pv[3];
            float p[16] = {pa.x, pa.y, pa.z, pa.w,  pb.x, pb.y, pb.z, pb.w,
                           pc.x, pc.y, pc.z, pc.w,  pd.x, pd.y, pd.z, pd.w};
            unsigned long long mp[8];
            #pragma unroll
            for (int q = 0; q < 8; q++) PACK2(mp[q], M[2 * q], M[2 * q + 1]);
            float N[16];
            #pragma unroll
            for (int jj = 0; jj < 16; jj++) {
                const ulonglong2* e2 = (const ulonglong2*)(Esh + jj * 16);
                ulonglong2 ea = e2[0], eb = e2[1], ec = e2[2], ed = e2[3];
                unsigned long long a0, a1;
                MUL2b(a0, mp[0], ea.x);
                FMA2(a0, mp[1], ea.y, a0);
                FMA2(a0, mp[2], eb.x, a0);
                FMA2(a0, mp[3], eb.y, a0);
                MUL2b(a1, mp[4], ec.x);
                FMA2(a1, mp[5], ec.y, a1);
                FMA2(a1, mp[6], ed.x, a1);
                FMA2(a1, mp[7], ed.y, a1);
                ADD2(a0, a0, a1);
                float2 f = unpack2(a0);
                N[jj] = (f.x + f.y) * p[jj];
            }
            #pragma unroll
            for (int jj = 0; jj < 16; jj++) M[jj] = N[jj];
        }
    }

    // Store transposed: Msh[c*256 + j*16 + i]
    {
        float* out = Msh + c * 256 + li;
        #pragma unroll
        for (int jj = 0; jj < 16; jj++) out[jj * 16] = M[jj];
    }
    __syncthreads();

    const float* pb = probs + (size_t)b * S_ * T_;

    if (warp == 0) {
        // serial combine from SMEM
        int j = lane & 15;
        float a[16];
        {
            const float4* p4 = (const float4*)pb;
            #pragma unroll
            for (int q = 0; q < 4; q++) {
                float4 v = p4[q];
                a[4 * q + 0] = v.x; a[4 * q + 1] = v.y;
                a[4 * q + 2] = v.z; a[4 * q + 3] = v.w;
            }
        }
        float mx = a[0];
        #pragma unroll
        for (int i = 1; i < 16; i++) mx = fmaxf(mx, a[i]);
        float L = mx;
        #pragma unroll
        for (int i = 0; i < 16; i++) a[i] = __expf(a[i] - mx);

        const ulonglong2* MT = (const ulonglong2*)Msh;
        #pragma unroll 1
        for (int cc = 0; cc < C_; cc++) {
            int t0 = (cc == 0) ? 1 : cc * CS_;
            int hi = cc * CS_ + CS_ - 1;
            int te = (len - 1 < hi) ? len - 1 : hi;
            int n  = te - t0 + 1;
            if (n > 0) {
                ulonglong2 mc0 = MT[cc * 64 + j * 4 + 0];
                ulonglong2 mc1 = MT[cc * 64 + j * 4 + 1];
                ulonglong2 mc2 = MT[cc * 64 + j * 4 + 2];
                ulonglong2 mc3 = MT[cc * 64 + j * 4 + 3];
                unsigned long long ap[8];
                #pragma unroll
                for (int q = 0; q < 8; q++) PACK2(ap[q], a[2 * q], a[2 * q + 1]);
                unsigned long long a0, a1;
                MUL2b(a0, ap[0], mc0.x);
                FMA2(a0, ap[1], mc0.y, a0);
                FMA2(a0, ap[2], mc1.x, a0);
                FMA2(a0, ap[3], mc1.y, a0);
                MUL2b(a1, ap[4], mc2.x);
                FMA2(a1, ap[5], mc2.y, a1);
                FMA2(a1, ap[6], mc3.x, a1);
                FMA2(a1, ap[7], mc3.y, a1);
                ADD2(a0, a0, a1);
                float2 f = unpack2(a0);
                if (lane < 16) sA[j] = f.x + f.y;
                __syncwarp();
                {
                    const float4* s4 = (const float4*)sA;
                    #pragma unroll
                    for (int q = 0; q < 4; q++) {
                        float4 v = s4[q];
                        a[4 * q + 0] = v.x; a[4 * q + 1] = v.y;
                        a[4 * q + 2] = v.z; a[4 * q + 3] = v.w;
                    }
                }
                __syncwarp();
                float mm = a[0];
                #pragma unroll
                for (int i = 1; i < 16; i++) mm = fmaxf(mm, a[i]);
                float r = __frcp_rn(mm);
                #pragma unroll
                for (int i = 0; i < 16; i++) a[i] *= r;
                L += __logf(mm) + (float)n * LN16_;
            }
        }
        float ssum = 0.f;
        #pragma unroll
        for (int i = 0; i < 16; i++) ssum += a[i];
        float log_norm = L + __logf(ssum);
        if (lane == 0) scp[0] = -log_norm;   // stash; scores added below
        __syncwarp();
    } else {
        // scores: threads 32..511 cover s = tid-32 and (tid<64: s+480)
        const int* tg = tags + b * S_;
        float sc = 0.f;
        int s = tid - 32;
        if (s < len) {
            int t = tg[s];
            sc += pb[s * T_ + t];
            if (s >= 1) sc += trans[tg[s - 1] * T_ + t];
        }
        if (tid < 64) {
            int s2 = tid - 32 + 480;
            if (s2 < len) {
                int t = tg[s2];
                sc += pb[s2 * T_ + t];
                sc += trans[tg[s2 - 1] * T_ + t];
            }
        }
        #pragma unroll
        for (int o = 16; o; o >>= 1) sc += __shfl_xor_sync(FULL_, sc, o);
        if (lane == 0) scp[warp] = sc;
    }
    __syncthreads();

    if (tid == 0) {
        float tot = 0.f;
        #pragma unroll
        for (int q = 0; q < 16; q++) tot += scp[q];
        out_ll[b]   = tot;          // scp[0] held -log_norm
        out_lens[b] = (float)len;
    }
}

// ---------------------------------------------------------------------------
// Launch.  Output layout: probs [0,524288) | lens [524288,524352) | ll [...)
// ---------------------------------------------------------------------------
extern "C" void kernel_launch(void* const* d_in, const int* in_sizes, int n_in,
                              void* d_out, int out_size) {
    const int*   text  = (const int*)  d_in[0];
    const int*   tags  = (const int*)  d_in[1];
    const float* embed = (const float*)d_in[2];
    const float* W     = (const float*)d_in[3];
    const float* bias  = (const float*)d_in[4];
    const float* trans = (const float*)d_in[5];

    float* out      = (float*)d_out;
    float* probs    = out;
    float* out_lens = out + B_ * S_ * T_;
    float* out_ll   = out_lens + B_;

    int smem_probs = TILE_ * EMB_ * 4 + (K4_ + 1) * T_ * 16 + T_ * 4 + TILE_ * 4
                   + TILE_ * T_ * 4;
    int smem_crf   = (C_ * 256 + 16 * 512 + 256 + 16 + 16 + 16) * 4;

    static int configured = -1;
    if (configured < 0) {
        cudaFuncSetAttribute(probs_kernel,
                             cudaFuncAttributeMaxDynamicSharedMemorySize, smem_probs);
        cudaFuncSetAttribute(crf_kernel,
                             cudaFuncAttributeMaxDynamicSharedMemorySize, smem_crf);
        configured = 1;
    }

    probs_kernel<<<(B_ * S_) / TILE_, 512, smem_probs>>>(text, embed, W, bias, probs);
    crf_kernel  <<<B_, 512, smem_crf>>>(text, tags, probs, trans, out_lens, out_ll);
}

// round 11
// speedup vs baseline: 1.9154x; 1.0268x over previous
#include <cuda_runtime.h>

// Problem constants
#define B_      64
#define S_      512
#define EMB_    300
#define T_      16
#define K4_     75          // EMB_/4
#define ROWF4_  77          // padded float4 row stride for staged embed (conflict-free)
#define C_      32          // chunks per batch
#define CS_     16          // steps per chunk
#define TILE_   64          // tokens per block in probs kernel
#define FULL_   0xffffffffu
#define LN16_   2.7725887222397811f

// Packed f32x2 helpers
#define FMA2(d, a, b, c) asm("fma.rn.f32x2 %0, %1, %2, %3;" : "=l"(d) : "l"(a), "l"(b), "l"(c))
#define MUL2b(d, a, b)   asm("mul.rn.f32x2 %0, %1, %2;"     : "=l"(d) : "l"(a), "l"(b))
#define ADD2(d, a, b)    asm("add.rn.f32x2 %0, %1, %2;"     : "=l"(d) : "l"(a), "l"(b))
#define PACK2(d, lo, hi) asm("mov.b64 %0, {%1, %2};"        : "=l"(d) : "f"(lo), "f"(hi))

__device__ __forceinline__ float2 unpack2(unsigned long long v) {
    float2 f;
    asm("mov.b64 {%0, %1}, %2;" : "=f"(f.x), "=f"(f.y) : "l"(v));
    return f;
}

// Scratch: per-(batch,chunk) transfer matrices, transposed:
// g_M[m*256 + j*16 + i] = M_m[i][j]
__device__ float g_M[B_ * C_ * 256];

// ---------------------------------------------------------------------------
// Kernel 1: probs = embed[text] @ W + b.
// 256 threads, 64-token tile, PER-THREAD-TOKEN: thread (kq = tid>>6,
// tok = tid&63) accumulates all 16 outputs of its token over k4 in
// [kq*19, ...).  Warp = 32 consecutive tokens, same kq -> the e-LDS.128 is
// conflict-free (row stride 77 float4, 5*tok mod 8 permutes 16B groups).
// W reads are warp-uniform broadcast LDS.128.  FMA2 is the binding pipe.
// Partials merged through SMEM (aliases dead W4 region).
// ---------------------------------------------------------------------------
__global__ void __launch_bounds__(256) probs_kernel(const int*   __restrict__ text,
                                                    const float* __restrict__ embed,
                                                    const float* __restrict__ W,
                                                    const float* __restrict__ bias,
                                                    float*       __restrict__ probs) {
    extern __shared__ float smem[];
    float*      esh  = smem;                                   // 64*77 float4
    ulonglong2* W4   = (ulonglong2*)(smem + TILE_ * ROWF4_ * 4); // 75*16
    float*      part = (float*)W4;                             // alias, post-loop
    float*      bsh  = (float*)(W4 + K4_ * T_);                // 16
    int*        tsh  = (int*)(bsh + T_);                       // 64

    int tid = threadIdx.x;
    int tb  = blockIdx.x * TILE_;

    if (tid < TILE_) tsh[tid] = text[tb + tid];

    // stage W: W4[k][j] = {(W[4k][j],W[4k+1][j]), (W[4k+2][j],W[4k+3][j])}
    {
        float* wf = (float*)W4;
        for (int idx = tid; idx < EMB_ * T_; idx += 256) {
            int d = idx >> 4, j = idx & 15;
            wf[((d >> 2) * T_ + j) * 4 + (d & 3)] = W[idx];
        }
        if (tid < T_) bsh[tid] = bias[tid];
    }
    __syncthreads();

    // stage 64 embed rows (padded stride), 4 threads per row, coalesced
    {
        int r = tid >> 2, c0 = tid & 3;
        const float4* src = (const float4*)(embed + (size_t)tsh[r] * EMB_);
        float4*       dst = (float4*)esh + r * ROWF4_;
        #pragma unroll
        for (int q = 0; q < 19; q++) {
            int c = c0 + 4 * q;
            if (c < K4_) dst[c] = src[c];
        }
    }
    __syncthreads();

    int kq  = tid >> 6;          // 0..3
    int tok = tid & 63;
    int kb  = kq * 19;
    int ke  = (kq == 3) ? K4_ : kb + 19;

    const ulonglong2* erow = (const ulonglong2*)((float4*)esh + tok * ROWF4_);

    unsigned long long acc[16];
    #pragma unroll
    for (int j = 0; j < 16; j++) acc[j] = 0ull;

    ulonglong2 e = erow[kb];
    #pragma unroll 2
    for (int k = kb; k < ke; k++) {
        ulonglong2 en = erow[k + 1];     // pad keeps this in-bounds
        const ulonglong2* wk = W4 + k * T_;
        #pragma unroll
        for (int j = 0; j < 16; j++) {
            ulonglong2 w = wk[j];
            FMA2(acc[j], e.x, w.x, acc[j]);
            FMA2(acc[j], e.y, w.y, acc[j]);
        }
        e = en;
    }

    float r16[16];
    #pragma unroll
    for (int j = 0; j < 16; j++) {
        float2 f = unpack2(acc[j]);
        r16[j] = f.x + f.y;
    }

    __syncthreads();    // everyone done reading W4 before aliasing as part

    {
        float4* myp = (float4*)(part + (kq * 64 + tok) * 16);
        #pragma unroll
        for (int q = 0; q < 4; q++)
            myp[q] = make_float4(r16[4*q], r16[4*q+1], r16[4*q+2], r16[4*q+3]);
    }
    __syncthreads();

    // merge: thread handles 4 outputs (otok, j0..j0+3)
    {
        int otok = tid >> 2, j0 = (tid & 3) * 4;
        float4 v = *(const float4*)(part + (0 * 64 + otok) * 16 + j0);
        #pragma unroll
        for (int q = 1; q < 4; q++) {
            float4 u = *(const float4*)(part + (q * 64 + otok) * 16 + j0);
            v.x += u.x; v.y += u.y; v.z += u.z; v.w += u.w;
        }
        v.x += bsh[j0 + 0]; v.y += bsh[j0 + 1];
        v.z += bsh[j0 + 2]; v.w += bsh[j0 + 3];
        *(float4*)(probs + (size_t)(tb + otok) * T_ + j0) = v;
    }
}

// ---------------------------------------------------------------------------
// Kernel 2: per-(batch,chunk) transfer-matrix products.
// grid 256 x 128: 8 matrices per block (half-warp per matrix) -> all SMs busy.
// ---------------------------------------------------------------------------
__global__ void __launch_bounds__(128) chunk_kernel(const int*   __restrict__ text,
                                                    const float* __restrict__ probs,
                                                    const float* __restrict__ trans) {
    __shared__ float Esh[256];       // Esh[j*16+k] = exp(trans[k][j])
    __shared__ float psh[4][512];

    int tid = threadIdx.x;
    for (int idx = tid; idx < 256; idx += 128) {
        int k = idx >> 4, jj = idx & 15;
        Esh[jj * 16 + k] = __expf(trans[idx]);
    }

    int warp = tid >> 5, lane = tid & 31;
    int half = lane >> 4, li = lane & 15;
    int m = blockIdx.x * 8 + warp * 2 + half;
    int b = m >> 5, c = m & (C_ - 1);

    // len for batch b
    const int4* tx4 = (const int4*)(text + b * S_);
    int cnt = 0;
    #pragma unroll
    for (int q = 0; q < 8; q++) {
        int4 v = tx4[li + q * 16];
        cnt += (v.x != 0) + (v.y != 0) + (v.z != 0) + (v.w != 0);
    }
    #pragma unroll
    for (int o = 8; o; o >>= 1) cnt += __shfl_xor_sync(FULL_, cnt, o);
    int len = cnt;

    // Stage exp(emit)/16 for this chunk's 16 steps
    {
        const float4* p4 = (const float4*)(probs + ((size_t)b * S_ + c * CS_) * T_);
        float* myp = &psh[warp][half * 256];
        #pragma unroll
        for (int q = 0; q < 4; q++) {
            float4 v = p4[li + q * 16];
            int o4 = (li + q * 16) * 4;
            myp[o4 + 0] = __expf(v.x) * 0.0625f;
            myp[o4 + 1] = __expf(v.y) * 0.0625f;
            myp[o4 + 2] = __expf(v.z) * 0.0625f;
            myp[o4 + 3] = __expf(v.w) * 0.0625f;
        }
    }
    __syncthreads();

    float M[16];
    #pragma unroll
    for (int jj = 0; jj < 16; jj++) M[jj] = (jj == li) ? 1.f : 0.f;

    const float* myp = &psh[warp][half * 256];
    #pragma unroll 1
    for (int dt = 0; dt < CS_; dt++) {
        int t = c * CS_ + dt;
        if (t >= 1 && t < len) {
            const float4* pv = (const float4*)(myp + dt * 16);
            float4 pa = pv[0], pb = pv[1], pc = pv[2], pd = pv[3];
            float p[16] = {pa.x, pa.y, pa.z, pa.w,  pb.x, pb.y, pb.z, pb.w,
                           pc.x, pc.y, pc.z, pc.w,  pd.x, pd.y, pd.z, pd.w};
            unsigned long long mp[8];
            #pragma unroll
            for (int q = 0; q < 8; q++) PACK2(mp[q], M[2 * q], M[2 * q + 1]);
            float N[16];
            #pragma unroll
            for (int jj = 0; jj < 16; jj++) {
                const ulonglong2* e2 = (const ulonglong2*)(Esh + jj * 16);
                ulonglong2 ea = e2[0], eb = e2[1], ec = e2[2], ed = e2[3];
                unsigned long long a0, a1;
                MUL2b(a0, mp[0], ea.x);
                FMA2(a0, mp[1], ea.y, a0);
                FMA2(a0, mp[2], eb.x, a0);
                FMA2(a0, mp[3], eb.y, a0);
                MUL2b(a1, mp[4], ec.x);
                FMA2(a1, mp[5], ec.y, a1);
                FMA2(a1, mp[6], ed.x, a1);
                FMA2(a1, mp[7], ed.y, a1);
                ADD2(a0, a0, a1);
                float2 f = unpack2(a0);
                N[jj] = (f.x + f.y) * p[jj];
            }
            #pragma unroll
            for (int jj = 0; jj < 16; jj++) M[jj] = N[jj];
        }
    }

    float* out = g_M + (size_t)m * 256 + li;
    #pragma unroll
    for (int jj = 0; jj < 16; jj++) out[jj * 16] = M[jj];
}

// ---------------------------------------------------------------------------
// Kernel 3: combine + scores.  256 threads per batch row.
// Warp 0: serial combine over 32 chunk matrices (prefetched from L2).
// Warps 1-7: unary+binary scores in parallel.  Lens via ballot.
// ---------------------------------------------------------------------------
__global__ void __launch_bounds__(256) combine_kernel(const int*   __restrict__ text,
                                                      const int*   __restrict__ tags,
                                                      const float* __restrict__ probs,
                                                      const float* __restrict__ trans,
                                                      float*       __restrict__ out_lens,
                                                      float*       __restrict__ out_ll) {
    __shared__ float sA[16];
    __shared__ float scp[8];
    __shared__ int   cnt[8];

    int tid  = threadIdx.x;
    int warp = tid >> 5, lane = tid & 31;
    int b    = blockIdx.x;

    // lens via ballot: thread covers s = tid and s = tid + 256
    {
        unsigned b0 = __ballot_sync(FULL_, text[b * S_ + tid] != 0);
        unsigned b1 = __ballot_sync(FULL_, text[b * S_ + tid + 256] != 0);
        if (lane == 0) cnt[warp] = __popc(b0) + __popc(b1);
    }
    __syncthreads();
    int len = 0;
    #pragma unroll
    for (int q = 0; q < 8; q++) len += cnt[q];

    const float* pb = probs + (size_t)b * S_ * T_;

    if (warp == 0) {
        int j = lane & 15;
        float a[16];
        {
            const float4* p4 = (const float4*)pb;
            #pragma unroll
            for (int q = 0; q < 4; q++) {
                float4 v = p4[q];
                a[4*q+0] = v.x; a[4*q+1] = v.y; a[4*q+2] = v.z; a[4*q+3] = v.w;
            }
        }
        float mx = a[0];
        #pragma unroll
        for (int i = 1; i < 16; i++) mx = fmaxf(mx, a[i]);
        float L = mx;
        #pragma unroll
        for (int i = 0; i < 16; i++) a[i] = __expf(a[i] - mx);

        const ulonglong2* MT = (const ulonglong2*)(g_M + (size_t)b * C_ * 256);
        ulonglong2 mc[4];
        #pragma unroll
        for (int q = 0; q < 4; q++) mc[q] = MT[j * 4 + q];

        #pragma unroll 1
        for (int c = 0; c < C_; c++) {
            ulonglong2 mn[4];
            if (c + 1 < C_) {
                #pragma unroll
                for (int q = 0; q < 4; q++) mn[q] = MT[(c + 1) * 64 + j * 4 + q];
            }
            int t0 = (c == 0) ? 1 : c * CS_;
            int hi = c * CS_ + CS_ - 1;
            int te = (len - 1 < hi) ? len - 1 : hi;
            int n  = te - t0 + 1;
            if (n > 0) {
                unsigned long long ap[8];
                #pragma unroll
                for (int q = 0; q < 8; q++) PACK2(ap[q], a[2*q], a[2*q+1]);
                unsigned long long a0, a1;
                MUL2b(a0, ap[0], mc[0].x);
                FMA2(a0, ap[1], mc[0].y, a0);
                FMA2(a0, ap[2], mc[1].x, a0);
                FMA2(a0, ap[3], mc[1].y, a0);
                MUL2b(a1, ap[4], mc[2].x);
                FMA2(a1, ap[5], mc[2].y, a1);
                FMA2(a1, ap[6], mc[3].x, a1);
                FMA2(a1, ap[7], mc[3].y, a1);
                ADD2(a0, a0, a1);
                float2 f = unpack2(a0);
                if (lane < 16) sA[j] = f.x + f.y;
                __syncwarp();
                {
                    const float4* s4 = (const float4*)sA;
                    #pragma unroll
                    for (int q = 0; q < 4; q++) {
                        float4 v = s4[q];
                        a[4*q+0] = v.x; a[4*q+1] = v.y;
                        a[4*q+2] = v.z; a[4*q+3] = v.w;
                    }
                }
                __syncwarp();
                float mm = a[0];
                #pragma unroll
                for (int i = 1; i < 16; i++) mm = fmaxf(mm, a[i]);
                float r = __frcp_rn(mm);
                #pragma unroll
                for (int i = 0; i < 16; i++) a[i] *= r;
                L += __logf(mm) + (float)n * LN16_;
            }
            #pragma unroll
            for (int q = 0; q < 4; q++) mc[q] = mn[q];
        }
        float ssum = 0.f;
        #pragma unroll
        for (int i = 0; i < 16; i++) ssum += a[i];
        if (lane == 0) scp[0] = -(L + __logf(ssum));
    } else {
        // scores: t = tid-32 in 0..223 covers s = t, t+224, (t<64: t+448)
        const int* tg = tags + b * S_;
        float sc = 0.f;
        int t = tid - 32;
        {
            int s = t;
            if (s < len) {
                int tg1 = tg[s];
                sc += pb[s * T_ + tg1];
                if (s >= 1) sc += trans[tg[s - 1] * T_ + tg1];
            }
        }
        {
            int s = t + 224;
            if (s < len) {
                int tg1 = tg[s];
                sc += pb[s * T_ + tg1];
                sc += trans[tg[s - 1] * T_ + tg1];
            }
        }
        if (t < 64) {
            int s = t + 448;
            if (s < len) {
                int tg1 = tg[s];
                sc += pb[s * T_ + tg1];
                sc += trans[tg[s - 1] * T_ + tg1];
            }
        }
        #pragma unroll
        for (int o = 16; o; o >>= 1) sc += __shfl_xor_sync(FULL_, sc, o);
        if (lane == 0) scp[warp] = sc;
    }
    __syncthreads();

    if (tid == 0) {
        float tot = 0.f;
        #pragma unroll
        for (int q = 0; q < 8; q++) tot += scp[q];
        out_ll[b]   = tot;
        out_lens[b] = (float)len;
    }
}

// ---------------------------------------------------------------------------
// Launch.  Output layout: probs [0,524288) | lens [524288,524352) | ll [...)
// ---------------------------------------------------------------------------
extern "C" void kernel_launch(void* const* d_in, const int* in_sizes, int n_in,
                              void* d_out, int out_size) {
    const int*   text  = (const int*)  d_in[0];
    const int*   tags  = (const int*)  d_in[1];
    const float* embed = (const float*)d_in[2];
    const float* W     = (const float*)d_in[3];
    const float* bias  = (const float*)d_in[4];
    const float* trans = (const float*)d_in[5];

    float* out      = (float*)d_out;
    float* probs    = out;
    float* out_lens = out + B_ * S_ * T_;
    float* out_ll   = out_lens + B_;

    int smem_probs = TILE_ * ROWF4_ * 16      // esh
                   + K4_ * T_ * 16            // W4 (aliased by part)
                   + T_ * 4 + TILE_ * 4;      // bsh + tsh

    static int configured = -1;
    if (configured < 0) {
        cudaFuncSetAttribute(probs_kernel,
                             cudaFuncAttributeMaxDynamicSharedMemorySize, smem_probs);
        configured = 1;
    }

    probs_kernel  <<<(B_ * S_) / TILE_, 256, smem_probs>>>(text, embed, W, bias, probs);
    chunk_kernel  <<<(B_ * C_) / 8, 128>>>(text, probs, trans);
    combine_kernel<<<B_, 256>>>(text, tags, probs, trans, out_lens, out_ll);
}